// round 5
// baseline (speedup 1.0000x reference)
#include <cuda_runtime.h>
#include <cuda_bf16.h>

// Problem constants (fixed by the reference)
#define Bq   4
#define Lq   100
#define Mq   2048
#define Eq   50
#define EX_SU_INV (1.0f / 1000.0f)
#define EX_TU_INV (1.0f / 86400.0f)

#define TM      512              // m-values per block tile
#define NCHUNK  (Mq / TM)        // 4
#define THREADS 800              // 25 warps; 800 % 25 == 0 -> phase-invariant, all lanes active
#define NV4     (TM * Eq / 4)    // 6400 float4 per block tile
#define NITER   (NV4 / THREADS)  // 8

__global__ __launch_bounds__(THREADS)
void ctr_embedding_kernel(const int*   __restrict__ traj_location,  // [B,L]
                          const float* __restrict__ mat2,           // [NLOC,M]
                          const float* __restrict__ vector,         // [B,L]
                          const int*   __restrict__ traj_length,    // [B]
                          const float* __restrict__ emb_su,         // [2,E]
                          const float* __restrict__ emb_sl,
                          const float* __restrict__ emb_tu,
                          const float* __restrict__ emb_tl,
                          float*       __restrict__ out)            // [B,L,M,E]
{
    __shared__ float  s_ds[TM];   // gathered mat2 slice (or zeros)
    __shared__ float2 s_bs[Eq];   // (base[e], slope[e])

    const int bl    = blockIdx.x;          // 0 .. B*L-1
    const int chunk = blockIdx.y;          // 0 .. NCHUNK-1
    const int b     = bl / Lq;
    const int l     = bl - b * Lq;
    const int m0    = chunk * TM;
    const int tid   = threadIdx.x;

    const bool valid = (l < traj_length[b]);

    // Stage gathered mat2 slice (or zeros) into smem, coalesced.
    if (valid) {
        const int loc = traj_location[bl] - 1;          // 1-based -> 0-based
        const float* row = mat2 + (size_t)loc * Mq + m0;
        if (tid < TM) s_ds[tid] = row[tid];
    } else {
        if (tid < TM) s_ds[tid] = 0.0f;
    }

    // Precompute per-(b,l) base/slope vectors over E.
    if (tid < Eq) {
        const int off = (valid ? 1 : 0) * Eq + tid;
        const float dt = vector[bl];
        const float tl = emb_tl[off], tu = emb_tu[off];
        const float sl = emb_sl[off], su = emb_su[off];
        // time_interval = tl + (tu - tl) * dt / EX_TU   (EX_TL = 0)
        const float time_i = fmaf(tu - tl, dt * EX_TU_INV, tl);
        // space_interval = sl + (su - sl) * ds / EX_SU  (EX_SL = 0)
        s_bs[tid] = make_float2(sl + time_i, (su - sl) * EX_SU_INV);
    }
    __syncthreads();

    // Full-lane phase-invariant mapping: thread t, iter i handles float4
    // index (800*i + t) of the 6400-float4 block tile. Since 800 % 25 == 0,
    // the e-phase (4t mod 100 -> mod 50) is loop-invariant, so each thread's
    // four (base, slope) constants live in registers. Exact index algebra:
    //   F = 3200*i + 4t,  m = 64*i + (4t)/50,  e = (4t+j) % 50.
    // A float4 crosses at most one m boundary; split-slope removes all SELs:
    //   r[j] = fma(sl_hi[j], d_hi, fma(sl_lo[j], d_lo, base[j])).
    // Inner loop: 2 broadcast-ish LDS.32 + 8 FFMA + 1 STG.128, 32/32 lanes.
    {
        const int f    = 4 * tid;              // float offset at iter 0
        const int m_lo = f / Eq;               // m (within tile) of float f, iter 0
        const int m_hi = (f + 3) / Eq;         // m of float f+3
        const int s    = Eq * (m_lo + 1) - f;  // first j using d_hi (>=4 => none)

        float base[4], sl_lo[4], sl_hi[4];
        #pragma unroll
        for (int j = 0; j < 4; j++) {
            const float2 c = s_bs[(f + j) % Eq];
            base[j]  = c.x;
            sl_lo[j] = (j < s) ? c.y : 0.0f;
            sl_hi[j] = c.y - sl_lo[j];
        }

        float* __restrict__ outp =
            out + ((size_t)bl * Mq + (size_t)m0) * Eq + f;

        #pragma unroll
        for (int i = 0; i < NITER; i++) {
            const float d_lo = s_ds[64 * i + m_lo];
            const float d_hi = s_ds[64 * i + m_hi];
            float r[4];
            #pragma unroll
            for (int j = 0; j < 4; j++)
                r[j] = fmaf(sl_hi[j], d_hi, fmaf(sl_lo[j], d_lo, base[j]));

            // 128-bit store, evict-first (output stream >> L2).
            asm volatile(
                "st.global.cs.v4.f32 [%0], {%1,%2,%3,%4};"
                :: "l"(outp + (size_t)i * (THREADS * 4)),
                   "f"(r[0]), "f"(r[1]), "f"(r[2]), "f"(r[3])
                : "memory");
        }
    }
}

extern "C" void kernel_launch(void* const* d_in, const int* in_sizes, int n_in,
                              void* d_out, int out_size)
{
    const int*   traj_location = (const int*)  d_in[0];
    const float* mat2          = (const float*)d_in[1];
    const float* vector        = (const float*)d_in[2];
    const int*   traj_length   = (const int*)  d_in[3];
    const float* emb_su        = (const float*)d_in[4];
    const float* emb_sl        = (const float*)d_in[5];
    const float* emb_tu        = (const float*)d_in[6];
    const float* emb_tl        = (const float*)d_in[7];
    float* out = (float*)d_out;

    dim3 grid(Bq * Lq, NCHUNK);
    ctr_embedding_kernel<<<grid, THREADS>>>(traj_location, mat2, vector,
                                            traj_length, emb_su, emb_sl,
                                            emb_tu, emb_tl, out);
}